// round 14
// baseline (speedup 1.0000x reference)
#include <cuda_runtime.h>

#define EPS_DEN 1e-9f
#define EPS_IN  1e-6f
#define TPB 128
#define NSTORE 24   // storage slots: max possible candidates -> appends need no bounds guard
#define NSORT 8     // sort/polygon width (convex-quad intersection has <= 8 vertices)

__device__ float        g_sum   = 0.0f;
__device__ unsigned int g_count = 0;

__device__ __forceinline__ void ce(unsigned &a, unsigned &b) {
    unsigned lo = min(a, b);
    unsigned hi = max(a, b);
    a = lo; b = hi;
}

__device__ __forceinline__ float frcp_fast(float x) {
    float r;
    asm("rcp.approx.f32 %0, %1;" : "=f"(r) : "f"(x));
    return r;
}

__global__ __launch_bounds__(TPB)
void iou_loss_kernel(const float4* __restrict__ gt,
                     const float4* __restrict__ det,
                     const int*   __restrict__ sizes,
                     float* __restrict__ out,
                     int B, int N, int nshift)
{
    __shared__ float px_sh[NSTORE][TPB];   // [slot][tid]: conflict-free for any slot
    __shared__ float py_sh[NSTORE][TPB];
    __shared__ float sdata[TPB / 32];

    int tid   = threadIdx.x;
    int idx   = blockIdx.x * TPB + tid;
    int total = B * N;
    float loss = 0.0f;

    if (idx < total) {
        int b = (nshift >= 0) ? (idx >> nshift) : (idx / N);
        float sx = (float)sizes[2 * b + 1];
        float sy = (float)sizes[2 * b + 0];

        float4 g0 = gt[2 * idx],  g1 = gt[2 * idx + 1];
        float4 d0 = det[2 * idx], d1 = det[2 * idx + 1];

        float p1x[4], p1y[4], p2x[4], p2y[4];
        p1x[0] = g0.x * sx; p1y[0] = g0.y * sy;
        p1x[1] = g0.z * sx; p1y[1] = g0.w * sy;
        p1x[2] = g1.x * sx; p1y[2] = g1.y * sy;
        p1x[3] = g1.z * sx; p1y[3] = g1.w * sy;
        p2x[0] = d0.x; p2y[0] = d0.y;
        p2x[1] = d0.z; p2y[1] = d0.w;
        p2x[2] = d1.x; p2y[2] = d1.y;
        p2x[3] = d1.z; p2y[3] = d1.w;

        float e1x[4], e1y[4], e2x[4], e2y[4];
        #pragma unroll
        for (int k = 0; k < 4; k++) {
            int k1 = (k + 1) & 3;
            e1x[k] = p1x[k1] - p1x[k]; e1y[k] = p1y[k1] - p1y[k];
            e2x[k] = p2x[k1] - p2x[k]; e2y[k] = p2y[k1] - p2y[k];
        }

        int   cnt = 0;
        float cx = 0.0f, cy = 0.0f;

        bool tpos[4], tneg[4], upos[4], uneg[4];
        #pragma unroll
        for (int k = 0; k < 4; k++) { tpos[k] = tneg[k] = upos[k] = uneg[k] = true; }

        // ---- fused: 16 edge-pair intersections + containment sign accumulation ----
        // Append bodies kept to exactly 2 stores so ptxas predicates them
        // (@P STS) instead of emitting BSSY/BSYNC divergence regions.
        #pragma unroll
        for (int i = 0; i < 4; i++) {
            float a0x = p1x[i], a0y = p1y[i];
            float d1x = e1x[i], d1y = e1y[i];
            #pragma unroll
            for (int j = 0; j < 4; j++) {
                float rx = p2x[j] - a0x, ry = p2y[j] - a0y;
                float den = d1x * e2y[j] - d1y * e2x[j];
                float tn  = rx * e2y[j] - ry * e2x[j];
                float un  = rx * d1y    - ry * d1x;

                tpos[i] = tpos[i] && (tn >= -EPS_IN);
                tneg[i] = tneg[i] && (tn <=  EPS_IN);
                upos[j] = upos[j] && (un <=  EPS_IN);
                uneg[j] = uneg[j] && (un >= -EPS_IN);

                bool  dok = fabsf(den) > EPS_DEN;
                float invd = frcp_fast(den);   // inf/nan t,u fail range tests; dok gates v
                float t = tn * invd;
                float u = un * invd;
                bool v = dok && (t >= 0.0f) && (t <= 1.0f)
                             && (u >= 0.0f) && (u <= 1.0f);
                float X = a0x + t * d1x;
                float Y = a0y + t * d1y;
                if (v) {
                    px_sh[cnt][tid] = X;
                    py_sh[cnt][tid] = Y;
                }
                cnt += v ? 1 : 0;
                cx  += v ? X : 0.0f;
                cy  += v ? Y : 0.0f;
            }
        }

        // ---- p1 vertices inside p2 ----
        #pragma unroll
        for (int q = 0; q < 4; q++) {
            bool v = tpos[q] || tneg[q];
            if (v) {
                px_sh[cnt][tid] = p1x[q];
                py_sh[cnt][tid] = p1y[q];
            }
            cnt += v ? 1 : 0;
            cx  += v ? p1x[q] : 0.0f;
            cy  += v ? p1y[q] : 0.0f;
        }

        // ---- p2 vertices inside p1 ----
        #pragma unroll
        for (int q = 0; q < 4; q++) {
            bool v = upos[q] || uneg[q];
            if (v) {
                px_sh[cnt][tid] = p2x[q];
                py_sh[cnt][tid] = p2y[q];
            }
            cnt += v ? 1 : 0;
            cx  += v ? p2x[q] : 0.0f;
            cy  += v ? p2y[q] : 0.0f;
        }

        // ---- quad areas ----
        float a1 = 0.0f, a2 = 0.0f;
        #pragma unroll
        for (int k = 0; k < 4; k++) {
            int k1 = (k + 1) & 3;
            a1 += p1x[k] * p1y[k1] - p1x[k1] * p1y[k];
            a2 += p2x[k] * p2y[k1] - p2x[k1] * p2y[k];
        }
        a1 = 0.5f * fabsf(a1);
        a2 = 0.5f * fabsf(a2);

        // ---- centroid ----
        float inv = frcp_fast((float)(cnt > 1 ? cnt : 1));
        cx *= inv;
        cy *= inv;
        int cslot = min(cnt, NSORT);

        // ---- keys: pseudo-angle (order-preserving uint), index in low 3 bits ----
        unsigned key[NSORT];
        #pragma unroll
        for (int k = 0; k < NSORT; k++) {
            float x = px_sh[k][tid], y = py_sh[k][tid];
            float dx = x - cx, dy = y - cy;
            float r = dx * frcp_fast(fabsf(dx) + fabsf(dy) + 1e-30f);
            float p = (dy >= 0.0f) ? (1.0f - r) : (r - 1.0f);
            unsigned u = __float_as_uint(p);
            u = (u & 0x80000000u) ? ~u : (u | 0x80000000u);
            unsigned kk = (u & 0xFFFFFFF8u) | (unsigned)k;
            key[k] = (k < cslot) ? kk : (0xFFFFFFF8u | (unsigned)k);
        }

        // ---- Batcher odd-even mergesort, n = 8 (19 compare-exchanges) ----
        {
            const int n = NSORT;
            #pragma unroll
            for (int p = 1; p < n; p *= 2) {
                #pragma unroll
                for (int k = p; k >= 1; k /= 2) {
                    #pragma unroll
                    for (int j = k % p; j <= n - 1 - k; j += 2 * k) {
                        #pragma unroll
                        for (int i = 0; i < k; i++) {
                            if (i <= n - j - k - 1) {
                                if ((i + j) / (2 * p) == (i + j + k) / (2 * p)) {
                                    ce(key[i + j], key[i + j + k]);
                                }
                            }
                        }
                    }
                }
            }
        }

        // ---- shoelace over sorted valid points ----
        int   o0  = (int)(key[0] & 7u);
        float s0x = px_sh[o0][tid], s0y = py_sh[o0][tid];
        float prevx = s0x, prevy = s0y;
        float s = 0.0f;
        #pragma unroll
        for (int i = 1; i < NSORT; i++) {
            int o = (int)(key[i] & 7u);
            bool v = i < cslot;
            float qx = v ? px_sh[o][tid] : s0x;
            float qy = v ? py_sh[o][tid] : s0y;
            s += prevx * qy - qx * prevy;
            prevx = qx;
            prevy = qy;
        }
        s += prevx * s0y - s0x * prevy;
        float inter = 0.5f * fabsf(s);
        if (cnt < 3) inter = 0.0f;

        float iou = inter / (a1 + a2 - inter + EPS_DEN);
        loss = 1.0f - iou;
    }

    // ---- block reduction ----
    #pragma unroll
    for (int off = 16; off > 0; off >>= 1)
        loss += __shfl_down_sync(0xffffffff, loss, off);
    int lane = tid & 31;
    int wid  = tid >> 5;
    if (lane == 0) sdata[wid] = loss;
    __syncthreads();
    if (wid == 0) {
        loss = (lane < TPB / 32) ? sdata[lane] : 0.0f;
        #pragma unroll
        for (int off = 16; off > 0; off >>= 1)
            loss += __shfl_down_sync(0xffffffff, loss, off);
    }

    // ---- global accumulation + last-block finalize (reset for next replay) ----
    if (tid == 0) {
        atomicAdd(&g_sum, loss);
        __threadfence();
        unsigned done = atomicInc(&g_count, gridDim.x - 1);  // wraps to 0 -> auto-reset
        if (done == gridDim.x - 1) {
            __threadfence();
            float s = *((volatile float*)&g_sum);
            out[0] = s / (float)total;
            g_sum = 0.0f;
        }
    }
}

extern "C" void kernel_launch(void* const* d_in, const int* in_sizes, int n_in,
                              void* d_out, int out_size)
{
    const float4* gt    = (const float4*)d_in[0];
    const float4* det   = (const float4*)d_in[1];
    const int*    sizes = (const int*)d_in[2];
    float*        out   = (float*)d_out;

    int B = in_sizes[2] / 2;
    int N = in_sizes[0] / (8 * B);
    int total = B * N;

    int nshift = -1;
    if ((N & (N - 1)) == 0) {
        nshift = 0;
        while ((1 << nshift) < N) nshift++;
    }

    int blocks = (total + TPB - 1) / TPB;
    iou_loss_kernel<<<blocks, TPB>>>(gt, det, sizes, out, B, N, nshift);
}

// round 15
// speedup vs baseline: 1.0286x; 1.0286x over previous
#include <cuda_runtime.h>

#define EPS_DEN 1e-9f
#define EPS_IN  1e-6f
#define TPB 64
#define NSTORE 24   // storage slots: max possible candidates -> appends need no bounds guard
#define NSORT 8     // sort/polygon width (convex-quad intersection has <= 8 vertices)

__device__ float        g_sum   = 0.0f;
__device__ unsigned int g_count = 0;

__device__ __forceinline__ void ce(unsigned &a, unsigned &b) {
    unsigned lo = min(a, b);
    unsigned hi = max(a, b);
    a = lo; b = hi;
}

__device__ __forceinline__ float frcp_fast(float x) {
    float r;
    asm("rcp.approx.f32 %0, %1;" : "=f"(r) : "f"(x));
    return r;
}

__global__ __launch_bounds__(TPB)
void iou_loss_kernel(const float4* __restrict__ gt,
                     const float4* __restrict__ det,
                     const int*   __restrict__ sizes,
                     float* __restrict__ out,
                     int B, int N, int nshift)
{
    __shared__ float px_sh[NSTORE][TPB];   // [slot][tid]: conflict-free for any slot
    __shared__ float py_sh[NSTORE][TPB];
    __shared__ float sdata[TPB / 32];

    int tid   = threadIdx.x;
    int idx   = blockIdx.x * TPB + tid;
    int total = B * N;
    float loss = 0.0f;

    if (idx < total) {
        int b = (nshift >= 0) ? (idx >> nshift) : (idx / N);
        float sx = (float)sizes[2 * b + 1];
        float sy = (float)sizes[2 * b + 0];

        float4 g0 = gt[2 * idx],  g1 = gt[2 * idx + 1];
        float4 d0 = det[2 * idx], d1 = det[2 * idx + 1];

        float p1x[4], p1y[4], p2x[4], p2y[4];
        p1x[0] = g0.x * sx; p1y[0] = g0.y * sy;
        p1x[1] = g0.z * sx; p1y[1] = g0.w * sy;
        p1x[2] = g1.x * sx; p1y[2] = g1.y * sy;
        p1x[3] = g1.z * sx; p1y[3] = g1.w * sy;
        p2x[0] = d0.x; p2y[0] = d0.y;
        p2x[1] = d0.z; p2y[1] = d0.w;
        p2x[2] = d1.x; p2y[2] = d1.y;
        p2x[3] = d1.z; p2y[3] = d1.w;

        float e1x[4], e1y[4], e2x[4], e2y[4];
        #pragma unroll
        for (int k = 0; k < 4; k++) {
            int k1 = (k + 1) & 3;
            e1x[k] = p1x[k1] - p1x[k]; e1y[k] = p1y[k1] - p1y[k];
            e2x[k] = p2x[k1] - p2x[k]; e2y[k] = p2y[k1] - p2y[k];
        }

        int   cnt = 0;
        float cx = 0.0f, cy = 0.0f;

        bool tpos[4], tneg[4], upos[4], uneg[4];
        #pragma unroll
        for (int k = 0; k < 4; k++) { tpos[k] = tneg[k] = upos[k] = uneg[k] = true; }

        // ---- fused: 16 edge-pair intersections + containment sign accumulation ----
        #pragma unroll
        for (int i = 0; i < 4; i++) {
            float a0x = p1x[i], a0y = p1y[i];
            float d1x = e1x[i], d1y = e1y[i];
            #pragma unroll
            for (int j = 0; j < 4; j++) {
                float rx = p2x[j] - a0x, ry = p2y[j] - a0y;
                float den = d1x * e2y[j] - d1y * e2x[j];
                float tn  = rx * e2y[j] - ry * e2x[j];
                float un  = rx * d1y    - ry * d1x;

                tpos[i] = tpos[i] && (tn >= -EPS_IN);
                tneg[i] = tneg[i] && (tn <=  EPS_IN);
                upos[j] = upos[j] && (un <=  EPS_IN);
                uneg[j] = uneg[j] && (un >= -EPS_IN);

                bool  dok = fabsf(den) > EPS_DEN;
                float invd = frcp_fast(den);   // inf/nan t,u fail range tests; dok gates v
                float t = tn * invd;
                float u = un * invd;
                bool v = dok && (t >= 0.0f) && (t <= 1.0f)
                             && (u >= 0.0f) && (u <= 1.0f);
                if (v) {
                    float X = a0x + t * d1x;
                    float Y = a0y + t * d1y;
                    px_sh[cnt][tid] = X;       // cnt < NSTORE always: no guard needed
                    py_sh[cnt][tid] = Y;
                    cnt++; cx += X; cy += Y;
                }
            }
        }

        // ---- p1 vertices inside p2 ----
        #pragma unroll
        for (int q = 0; q < 4; q++) {
            if (tpos[q] || tneg[q]) {
                px_sh[cnt][tid] = p1x[q];
                py_sh[cnt][tid] = p1y[q];
                cnt++; cx += p1x[q]; cy += p1y[q];
            }
        }

        // ---- p2 vertices inside p1 ----
        #pragma unroll
        for (int q = 0; q < 4; q++) {
            if (upos[q] || uneg[q]) {
                px_sh[cnt][tid] = p2x[q];
                py_sh[cnt][tid] = p2y[q];
                cnt++; cx += p2x[q]; cy += p2y[q];
            }
        }

        // ---- quad areas ----
        float a1 = 0.0f, a2 = 0.0f;
        #pragma unroll
        for (int k = 0; k < 4; k++) {
            int k1 = (k + 1) & 3;
            a1 += p1x[k] * p1y[k1] - p1x[k1] * p1y[k];
            a2 += p2x[k] * p2y[k1] - p2x[k1] * p2y[k];
        }
        a1 = 0.5f * fabsf(a1);
        a2 = 0.5f * fabsf(a2);

        // ---- centroid ----
        float inv = frcp_fast((float)(cnt > 1 ? cnt : 1));
        cx *= inv;
        cy *= inv;
        int cslot = min(cnt, NSORT);

        // ---- keys: pseudo-angle (order-preserving uint), index in low 3 bits ----
        unsigned key[NSORT];
        #pragma unroll
        for (int k = 0; k < NSORT; k++) {
            float x = px_sh[k][tid], y = py_sh[k][tid];
            float dx = x - cx, dy = y - cy;
            float r = dx * frcp_fast(fabsf(dx) + fabsf(dy) + 1e-30f);
            float p = (dy >= 0.0f) ? (1.0f - r) : (r - 1.0f);
            unsigned u = __float_as_uint(p);
            u = (u & 0x80000000u) ? ~u : (u | 0x80000000u);
            unsigned kk = (u & 0xFFFFFFF8u) | (unsigned)k;
            key[k] = (k < cslot) ? kk : (0xFFFFFFF8u | (unsigned)k);
        }

        // ---- Batcher odd-even mergesort, n = 8 (19 compare-exchanges) ----
        {
            const int n = NSORT;
            #pragma unroll
            for (int p = 1; p < n; p *= 2) {
                #pragma unroll
                for (int k = p; k >= 1; k /= 2) {
                    #pragma unroll
                    for (int j = k % p; j <= n - 1 - k; j += 2 * k) {
                        #pragma unroll
                        for (int i = 0; i < k; i++) {
                            if (i <= n - j - k - 1) {
                                if ((i + j) / (2 * p) == (i + j + k) / (2 * p)) {
                                    ce(key[i + j], key[i + j + k]);
                                }
                            }
                        }
                    }
                }
            }
        }

        // ---- shoelace over sorted valid points ----
        int   o0  = (int)(key[0] & 7u);
        float s0x = px_sh[o0][tid], s0y = py_sh[o0][tid];
        float prevx = s0x, prevy = s0y;
        float s = 0.0f;
        #pragma unroll
        for (int i = 1; i < NSORT; i++) {
            int o = (int)(key[i] & 7u);
            bool v = i < cslot;
            float qx = v ? px_sh[o][tid] : s0x;
            float qy = v ? py_sh[o][tid] : s0y;
            s += prevx * qy - qx * prevy;
            prevx = qx;
            prevy = qy;
        }
        s += prevx * s0y - s0x * prevy;
        float inter = 0.5f * fabsf(s);
        if (cnt < 3) inter = 0.0f;

        float iou = inter / (a1 + a2 - inter + EPS_DEN);
        loss = 1.0f - iou;
    }

    // ---- block reduction (TPB=64: 2 warps) ----
    #pragma unroll
    for (int off = 16; off > 0; off >>= 1)
        loss += __shfl_down_sync(0xffffffff, loss, off);
    int lane = tid & 31;
    int wid  = tid >> 5;
    if (lane == 0) sdata[wid] = loss;
    __syncthreads();

    // ---- global accumulation + last-block finalize (reset for next replay) ----
    if (tid == 0) {
        float bsum = sdata[0] + sdata[1];
        atomicAdd(&g_sum, bsum);
        __threadfence();
        unsigned done = atomicInc(&g_count, gridDim.x - 1);  // wraps to 0 -> auto-reset
        if (done == gridDim.x - 1) {
            __threadfence();
            float s = *((volatile float*)&g_sum);
            out[0] = s / (float)total;
            g_sum = 0.0f;
        }
    }
}

extern "C" void kernel_launch(void* const* d_in, const int* in_sizes, int n_in,
                              void* d_out, int out_size)
{
    const float4* gt    = (const float4*)d_in[0];
    const float4* det   = (const float4*)d_in[1];
    const int*    sizes = (const int*)d_in[2];
    float*        out   = (float*)d_out;

    int B = in_sizes[2] / 2;
    int N = in_sizes[0] / (8 * B);
    int total = B * N;

    int nshift = -1;
    if ((N & (N - 1)) == 0) {
        nshift = 0;
        while ((1 << nshift) < N) nshift++;
    }

    int blocks = (total + TPB - 1) / TPB;
    iou_loss_kernel<<<blocks, TPB>>>(gt, det, sizes, out, B, N, nshift);
}